// round 12
// baseline (speedup 1.0000x reference)
#include <cuda_runtime.h>
#include <cuda_fp16.h>
#include <cstdint>
#include <cstddef>

// Shapes (fixed)
#define NB 16
#define NM 128
#define NH 256
#define NE 128
#define NC 384
#define NROWS 2048
#define EDGE_GRID 148

// Scratch
__device__ float g_msgE[NROWS * NE];
// chunk-blocked fp16 operands: [kc][n=256][k=64], each 32KB chunk contiguous
__device__ half  g_WrB[6 * 256 * 64];
__device__ half  g_W0B[4 * 256 * 64];
__device__ half  g_W1B[4 * 256 * 64];
__device__ half  g_XB[NB * 2 * 256 * 64];

// ---------------------------------------------------------------------------
// helpers
// ---------------------------------------------------------------------------
__device__ __forceinline__ uint32_t h2u(half2 h) {
    return *reinterpret_cast<uint32_t*>(&h);
}
__device__ __forceinline__ uint2 f4toh4(float4 v) {
    return make_uint2(h2u(__floats2half2_rn(v.x, v.y)),
                      h2u(__floats2half2_rn(v.z, v.w)));
}
__device__ __forceinline__ void mma16h(float* d, const uint32_t* a, const uint32_t* b) {
    asm volatile(
        "mma.sync.aligned.m16n8k16.row.col.f32.f16.f16.f32 "
        "{%0,%1,%2,%3}, {%4,%5,%6,%7}, {%8,%9}, {%0,%1,%2,%3};"
        : "+f"(d[0]), "+f"(d[1]), "+f"(d[2]), "+f"(d[3])
        : "r"(a[0]), "r"(a[1]), "r"(a[2]), "r"(a[3]),
          "r"(b[0]), "r"(b[1]));
}

// ---------------------------------------------------------------------------
// cvt kernel: W (row-major [K][256]) / X_b ([128][256]) -> blocked fp16
//   out[(kc*256 + n)*64 + kl] = src[(kc*64+kl)*256 + n]
// grid 368: [0,48) Wr, [48,80) W0, [80,112) W1, [112,368) X.
// ---------------------------------------------------------------------------
__global__ __launch_bounds__(256)
void cvt_blocked(const float* __restrict__ Wr, const float* __restrict__ W0,
                 const float* __restrict__ W1, const float* __restrict__ X)
{
    __shared__ float tile[64][33];
    const int id = blockIdx.x;
    const float* src; half* dst; int kc, n0;
    if (id < 48)       { kc = id >> 3; n0 = (id & 7) * 32; src = Wr; dst = g_WrB; }
    else if (id < 80)  { int t = id - 48; kc = t >> 3; n0 = (t & 7) * 32;
                         src = W0; dst = g_W0B; }
    else if (id < 112) { int t = id - 80; kc = t >> 3; n0 = (t & 7) * 32;
                         src = W1; dst = g_W1B; }
    else {
        int t = id - 112;              // b(16) x kc(2) x nt(8)
        int b = t >> 4, tt = t & 15;
        kc = tt >> 3; n0 = (tt & 7) * 32;
        src = X + (size_t)b * 32768;
        dst = g_XB + (size_t)b * 32768;
    }
    const int c = threadIdx.x & 31, r8 = threadIdx.x >> 5;
    #pragma unroll
    for (int p = 0; p < 8; ++p) {
        int r = r8 + p * 8;
        tile[r][c] = src[(size_t)(kc * 64 + r) * 256 + n0 + c];
    }
    __syncthreads();
    const int nl = threadIdx.x >> 3, kl0 = (threadIdx.x & 7) * 8;
    half* o = dst + ((size_t)(kc * 256 + n0 + nl) * 64 + kl0);
    uint4 v;
    v.x = h2u(__floats2half2_rn(tile[kl0 + 0][nl], tile[kl0 + 1][nl]));
    v.y = h2u(__floats2half2_rn(tile[kl0 + 2][nl], tile[kl0 + 3][nl]));
    v.z = h2u(__floats2half2_rn(tile[kl0 + 4][nl], tile[kl0 + 5][nl]));
    v.w = h2u(__floats2half2_rn(tile[kl0 + 6][nl], tile[kl0 + 7][nl]));
    *(uint4*)o = v;
}

// ---------------------------------------------------------------------------
// Edge kernel: fp16 mma, SKEWED pipeline (compute(q) || STS(q+1) || LDG(q+2)).
// 512 thr = 16 warps (4 rg x 4 cg), persistent, 1 sync per quarter.
// Quarters occupy disjoint 32-col ranges of Es, so staging q+1 while
// computing q is race-free; the single loop-top sync fences visibility.
// ---------------------------------------------------------------------------
#define EH_PITCH 136
#define ES_OFF   0
#define WS_OFF   34816
#define AW_OFF   69632
#define RED_OFF  70656
#define SM_BYTES 72192

__device__ __forceinline__ void compute_quarter_h(const half* __restrict__ ap,
                                                  const half* __restrict__ bp,
                                                  float acc[2][4][4])
{
    #pragma unroll
    for (int ss = 0; ss < 2; ++ss) {
        const int kb = ss * 16;
        uint32_t a[2][4];
        #pragma unroll
        for (int m = 0; m < 2; ++m) {
            const half* p = ap + m * (16 * EH_PITCH) + kb;
            a[m][0] = *(const uint32_t*)(p);
            a[m][1] = *(const uint32_t*)(p + 8 * EH_PITCH);
            a[m][2] = *(const uint32_t*)(p + 8);
            a[m][3] = *(const uint32_t*)(p + 8 * EH_PITCH + 8);
        }
        uint32_t bq[4][2];
        #pragma unroll
        for (int n = 0; n < 4; ++n) {
            const half* p = bp + n * (8 * EH_PITCH) + kb;
            bq[n][0] = *(const uint32_t*)(p);
            bq[n][1] = *(const uint32_t*)(p + 8);
        }
        #pragma unroll
        for (int m = 0; m < 2; ++m)
            #pragma unroll
            for (int n = 0; n < 4; ++n)
                mma16h(acc[m][n], a[m], bq[n]);
    }
}

__global__ __launch_bounds__(512, 1)
void edge_msg_mma(const float* __restrict__ E,
                  const float* __restrict__ A,
                  const float* __restrict__ We,
                  const float* __restrict__ be,
                  float* __restrict__ msgE)
{
    extern __shared__ char smc[];
    half*  Es  = (half*)(smc + ES_OFF);
    half*  Ws  = (half*)(smc + WS_OFF);
    float* awb = (float*)(smc + AW_OFF);
    float* red = (float*)(smc + RED_OFF);

    const int tid  = threadIdx.x;
    const int lane = tid & 31;
    const int wid  = tid >> 5;
    const int rg   = wid >> 2;
    const int cg   = wid & 3;
    const int row0 = rg * 32;
    const int col0 = cg * 32;

    float be0[4], be1[4];
    #pragma unroll
    for (int n = 0; n < 4; ++n) {
        be0[n] = be[col0 + 8 * n + 2 * (lane & 3)];
        be1[n] = be[col0 + 8 * n + 2 * (lane & 3) + 1];
    }

    // We^T -> Ws[f][e] (once); fenced by first loop-top sync
    for (int idx = tid; idx < 8192; idx += 512) {
        int f = idx & 127;
        int e = (idx >> 7) * 2;
        *(half2*)(Ws + f * EH_PITCH + e) =
            __floats2half2_rn(We[(size_t)e * 128 + f], We[(size_t)(e + 1) * 128 + f]);
    }

    const int t0  = blockIdx.x;
    const int ntl = (NROWS - t0 + EDGE_GRID - 1) / EDGE_GRID;
    const int NG  = 4 * ntl;

    const int ech = (tid & 7) * 4;
    const int ir0 = tid >> 3;
    auto ldqg = [&](float4* r, int g) {
        const int t = t0 + (g >> 2) * EDGE_GRID;
        const float* src = E + (size_t)(t >> 7) * 2097152
                             + (size_t)ir0 * 16384
                             + (size_t)(t & 127) * 128 + (g & 3) * 32 + ech;
        r[0] = *(const float4*)(src);
        r[1] = *(const float4*)(src + (size_t)64 * 16384);
    };
    half* qdst0 = Es + ir0 * EH_PITCH + ech;
    auto stage = [&](const float4* r, int g) {
        half* qd = qdst0 + (g & 3) * 32;
        half2 h0 = __floats2half2_rn(r[0].x, r[0].y);
        half2 h1 = __floats2half2_rn(r[0].z, r[0].w);
        *(uint2*)(qd) = make_uint2(h2u(h0), h2u(h1));
        half2 h2 = __floats2half2_rn(r[1].x, r[1].y);
        half2 h3 = __floats2half2_rn(r[1].z, r[1].w);
        *(uint2*)(qd + 64 * EH_PITCH) = make_uint2(h2u(h2), h2u(h3));
    };

    // prologue: SMEM <- g=0; pre <- g=1
    float4 pre[2], nxt[2];
    ldqg(pre, 0);
    stage(pre, 0);
    if (NG > 1) ldqg(pre, 1);
    float awreg = (tid < 128)
        ? A[(size_t)(t0 >> 7) * 16384 + (size_t)tid * 128 + (t0 & 127)] : 0.f;

    float acc[2][4][4];
    #pragma unroll
    for (int m = 0; m < 2; ++m)
        #pragma unroll
        for (int n = 0; n < 4; ++n)
            #pragma unroll
            for (int q = 0; q < 4; ++q) acc[m][n][q] = 0.f;

    const half* aptr = Es + (row0 + (lane >> 2)) * EH_PITCH + (lane & 3) * 2;
    const half* bptr = Ws + (col0 + (lane >> 2)) * EH_PITCH + (lane & 3) * 2;

    for (int g = 0; g < NG; ++g) {
        __syncthreads();                        // stage(g) visible to all
        if (g + 2 < NG) ldqg(nxt, g + 2);

        if ((g & 3) == 0 && tid < 128) {
            const int kt = g >> 2;
            awb[(kt & 1) * 128 + tid] = awreg;
            if (kt + 1 < ntl) {
                const int tn = t0 + (kt + 1) * EDGE_GRID;
                awreg = A[(size_t)(tn >> 7) * 16384 + (size_t)tid * 128 + (tn & 127)];
            }
        }

        compute_quarter_h(aptr + (g & 3) * 32, bptr + (g & 3) * 32, acc);
        if (g + 1 < NG) stage(pre, g + 1);      // disjoint cols vs compute(g)
        pre[0] = nxt[0]; pre[1] = nxt[1];

        if ((g & 3) == 3) {
            // ---- epilogue for tile kt = g>>2 ----
            const int kt = g >> 2;
            const int t  = t0 + kt * EDGE_GRID;
            const float* aw = awb + (kt & 1) * 128;
            float p0[4], p1[4];
            #pragma unroll
            for (int n = 0; n < 4; ++n) { p0[n] = 0.f; p1[n] = 0.f; }
            #pragma unroll
            for (int m = 0; m < 2; ++m) {
                float w0 = aw[row0 + 16 * m + (lane >> 2)];
                float w1 = aw[row0 + 16 * m + (lane >> 2) + 8];
                #pragma unroll
                for (int n = 0; n < 4; ++n) {
                    p0[n] += w0 * fmaxf(acc[m][n][0] + be0[n], 0.f)
                           + w1 * fmaxf(acc[m][n][2] + be0[n], 0.f);
                    p1[n] += w0 * fmaxf(acc[m][n][1] + be1[n], 0.f)
                           + w1 * fmaxf(acc[m][n][3] + be1[n], 0.f);
                    acc[m][n][0] = 0.f; acc[m][n][1] = 0.f;
                    acc[m][n][2] = 0.f; acc[m][n][3] = 0.f;
                }
            }
            #pragma unroll
            for (int off = 4; off < 32; off <<= 1) {
                #pragma unroll
                for (int n = 0; n < 4; ++n) {
                    p0[n] += __shfl_xor_sync(0xffffffffu, p0[n], off);
                    p1[n] += __shfl_xor_sync(0xffffffffu, p1[n], off);
                }
            }
            if (rg > 0 && lane < 4) {
                #pragma unroll
                for (int n = 0; n < 4; ++n) {
                    int f = col0 + 8 * n + 2 * lane;
                    red[(rg - 1) * 128 + f]     = p0[n];
                    red[(rg - 1) * 128 + f + 1] = p1[n];
                }
            }
            __syncthreads();
            if (rg == 0 && lane < 4) {
                #pragma unroll
                for (int n = 0; n < 4; ++n) {
                    int f = col0 + 8 * n + 2 * lane;
                    msgE[(size_t)t * NE + f] =
                        p0[n] + red[f] + red[128 + f] + red[256 + f];
                    msgE[(size_t)t * NE + f + 1] =
                        p1[n] + red[f + 1] + red[128 + f + 1] + red[256 + f + 1];
                }
            }
        }
    }
}

// ---------------------------------------------------------------------------
// Fused MLP + msg_x: fp16 mma, scalar frag loads, 64-wide k-chunks from
// blocked global (coalesced). One CTA = 16 rows. grid 128, 8 warps.
// ---------------------------------------------------------------------------
#define AM_P  392
#define AST_P 136
#define FT_P  264
#define BS_P  72
#define OFF_AM  0
#define OFF_AST 12544
#define OFF_TS  16896
#define OFF_US  25344
#define OFF_BS0 33792
#define OFF_BS1 70656
#define FSM_BYTES 107520

// WB: blocked [nch][256][64]; staging: thread tid <- 64 contiguous halfs.
__device__ __forceinline__ void fgemm_h(const half* __restrict__ Asm, int PA,
                                        const half* __restrict__ WB,
                                        half* __restrict__ bs0,
                                        half* __restrict__ bs1,
                                        int nch, int tid, int lane, int wcol0,
                                        float acc[4][4])
{
    const half* wsrc = WB + (size_t)tid * 64;
    uint4 pw[8];
    #pragma unroll
    for (int q = 0; q < 8; ++q) pw[q] = *(const uint4*)(wsrc + q * 8);

    const half* apb = Asm + (lane >> 2) * PA + (lane & 3) * 2;

    for (int kc = 0; kc < nch; ++kc) {
        half* bd = ((kc & 1) ? bs1 : bs0) + tid * BS_P;
        #pragma unroll
        for (int q = 0; q < 8; ++q) *(uint4*)(bd + q * 8) = pw[q];
        if (kc + 1 < nch) {
            const half* ws = wsrc + (size_t)(kc + 1) * 16384;
            #pragma unroll
            for (int q = 0; q < 8; ++q) pw[q] = *(const uint4*)(ws + q * 8);
        }
        __syncthreads();

        const half* bp = ((kc & 1) ? bs1 : bs0)
                       + (wcol0 + (lane >> 2)) * BS_P + (lane & 3) * 2;
        const half* ap = apb + kc * 64;
        #pragma unroll
        for (int ss = 0; ss < 4; ++ss) {
            const half* pa = ap + ss * 16;
            uint32_t a[4];
            a[0] = *(const uint32_t*)(pa);
            a[1] = *(const uint32_t*)(pa + 8 * PA);
            a[2] = *(const uint32_t*)(pa + 8);
            a[3] = *(const uint32_t*)(pa + 8 * PA + 8);
            uint32_t bq[4][2];
            #pragma unroll
            for (int n = 0; n < 4; ++n) {
                const half* pb = bp + n * (8 * BS_P) + ss * 16;
                bq[n][0] = *(const uint32_t*)(pb);
                bq[n][1] = *(const uint32_t*)(pb + 8);
            }
            #pragma unroll
            for (int n = 0; n < 4; ++n) mma16h(acc[n], a, bq[n]);
        }
    }
}

__global__ __launch_bounds__(256)
void mlp_fused(const float* __restrict__ msgE,
               const float* __restrict__ X,
               const float* __restrict__ A,
               const float* __restrict__ epsp,
               const float* __restrict__ br, const float* __restrict__ b0,
               const float* __restrict__ b1,
               float* __restrict__ Out)
{
    extern __shared__ char fsc[];
    half* Am  = (half*)(fsc + OFF_AM);
    half* AsT = (half*)(fsc + OFF_AST);
    half* Ts  = (half*)(fsc + OFF_TS);
    half* Us  = (half*)(fsc + OFF_US);
    half* Bs0 = (half*)(fsc + OFF_BS0);
    half* Bs1 = (half*)(fsc + OFF_BS1);

    const int r0   = blockIdx.x * 16;
    const int b    = r0 >> 7;
    const int j0   = r0 & 127;
    const int tid  = threadIdx.x;
    const int lane = tid & 31;
    const int wid  = tid >> 5;
    const int wcol0 = wid * 32;

    for (int idx = tid; idx < 2048; idx += 256) {
        int i = idx >> 4, jj = idx & 15;
        AsT[jj * AST_P + i] =
            __float2half(A[(size_t)b * 16384 + (size_t)i * 128 + j0 + jj]);
    }
    {
        const int row = tid >> 4;
        const int c   = (tid & 15) * 8;
        const float* src = msgE + (size_t)(r0 + row) * NE + c;
        half* dst = Am + row * AM_P + 256 + c;
        *(uint2*)(dst)     = f4toh4(*(const float4*)(src));
        *(uint2*)(dst + 4) = f4toh4(*(const float4*)(src + 4));
    }
    __syncthreads();

    float acc[4][4];
    #pragma unroll
    for (int n = 0; n < 4; ++n)
        #pragma unroll
        for (int q = 0; q < 4; ++q) acc[n][q] = 0.f;

    const int erow = lane >> 2;
    const int ecol = 2 * (lane & 3);

    // ---- msg_x = AsT @ X_b -> Am cols 0..255 ----
    fgemm_h(AsT, AST_P, g_XB + (size_t)b * 32768, Bs0, Bs1,
            2, tid, lane, wcol0, acc);
    #pragma unroll
    for (int n = 0; n < 4; ++n) {
        int col = wcol0 + 8 * n + ecol;
        *(uint32_t*)(Am + erow * AM_P + col) =
            h2u(__floats2half2_rn(acc[n][0], acc[n][1]));
        *(uint32_t*)(Am + (erow + 8) * AM_P + col) =
            h2u(__floats2half2_rn(acc[n][2], acc[n][3]));
        acc[n][0] = acc[n][1] = acc[n][2] = acc[n][3] = 0.f;
    }
    __syncthreads();

    // ---- layer 1: t = (1+eps)*X + relu(Am@Wr + br) ----
    fgemm_h(Am, AM_P, g_WrB, Bs0, Bs1, 6, tid, lane, wcol0, acc);
    {
        const float epsv = 1.f + *epsp;
        #pragma unroll
        for (int n = 0; n < 4; ++n) {
            int col = wcol0 + 8 * n + ecol;
            float v00 = fmaxf(acc[n][0] + br[col], 0.f)
                      + epsv * X[(size_t)(r0 + erow) * 256 + col];
            float v01 = fmaxf(acc[n][1] + br[col + 1], 0.f)
                      + epsv * X[(size_t)(r0 + erow) * 256 + col + 1];
            float v10 = fmaxf(acc[n][2] + br[col], 0.f)
                      + epsv * X[(size_t)(r0 + erow + 8) * 256 + col];
            float v11 = fmaxf(acc[n][3] + br[col + 1], 0.f)
                      + epsv * X[(size_t)(r0 + erow + 8) * 256 + col + 1];
            *(uint32_t*)(Ts + erow * FT_P + col)       = h2u(__floats2half2_rn(v00, v01));
            *(uint32_t*)(Ts + (erow + 8) * FT_P + col) = h2u(__floats2half2_rn(v10, v11));
            acc[n][0] = acc[n][1] = acc[n][2] = acc[n][3] = 0.f;
        }
    }
    __syncthreads();

    // ---- layer 2: u = relu(t@W0 + b0) ----
    fgemm_h(Ts, FT_P, g_W0B, Bs0, Bs1, 4, tid, lane, wcol0, acc);
    #pragma unroll
    for (int n = 0; n < 4; ++n) {
        int col = wcol0 + 8 * n + ecol;
        *(uint32_t*)(Us + erow * FT_P + col) = h2u(__floats2half2_rn(
            fmaxf(acc[n][0] + b0[col], 0.f), fmaxf(acc[n][1] + b0[col + 1], 0.f)));
        *(uint32_t*)(Us + (erow + 8) * FT_P + col) = h2u(__floats2half2_rn(
            fmaxf(acc[n][2] + b0[col], 0.f), fmaxf(acc[n][3] + b0[col + 1], 0.f)));
        acc[n][0] = acc[n][1] = acc[n][2] = acc[n][3] = 0.f;
    }
    __syncthreads();

    // ---- layer 3: out = relu(u@W1 + b1) ----
    fgemm_h(Us, FT_P, g_W1B, Bs0, Bs1, 4, tid, lane, wcol0, acc);
    #pragma unroll
    for (int n = 0; n < 4; ++n) {
        int col = wcol0 + 8 * n + ecol;
        float2 v0 = make_float2(fmaxf(acc[n][0] + b1[col], 0.f),
                                fmaxf(acc[n][1] + b1[col + 1], 0.f));
        float2 v1 = make_float2(fmaxf(acc[n][2] + b1[col], 0.f),
                                fmaxf(acc[n][3] + b1[col + 1], 0.f));
        *(float2*)(Out + (size_t)(r0 + erow) * 256 + col)     = v0;
        *(float2*)(Out + (size_t)(r0 + erow + 8) * 256 + col) = v1;
    }
}

// ---------------------------------------------------------------------------
extern "C" void kernel_launch(void* const* d_in, const int* in_sizes, int n_in,
                              void* d_out, int out_size)
{
    const float* X   = (const float*)d_in[0];
    const float* E   = (const float*)d_in[1];
    const float* A   = (const float*)d_in[2];
    const float* eps = (const float*)d_in[3];
    const float* We  = (const float*)d_in[4];
    const float* be  = (const float*)d_in[5];
    const float* Wr  = (const float*)d_in[6];
    const float* br  = (const float*)d_in[7];
    const float* W0  = (const float*)d_in[8];
    const float* b0  = (const float*)d_in[9];
    const float* W1  = (const float*)d_in[10];
    const float* b1  = (const float*)d_in[11];
    float* out = (float*)d_out;

    void* pmsg;
    cudaGetSymbolAddress(&pmsg, g_msgE);
    float* msgE = (float*)pmsg;

    cudaFuncSetAttribute(edge_msg_mma,
                         cudaFuncAttributeMaxDynamicSharedMemorySize, SM_BYTES);
    cudaFuncSetAttribute(mlp_fused,
                         cudaFuncAttributeMaxDynamicSharedMemorySize, FSM_BYTES);

    cvt_blocked<<<368, 256>>>(Wr, W0, W1, X);
    edge_msg_mma<<<EDGE_GRID, 512, SM_BYTES>>>(E, A, We, be, msgE);
    mlp_fused<<<128, 256, FSM_BYTES>>>(msgE, X, A, eps, br, b0, b1, out);
}

// round 13
// speedup vs baseline: 1.0822x; 1.0822x over previous
#include <cuda_runtime.h>
#include <cuda_fp16.h>
#include <cstdint>
#include <cstddef>

// Shapes (fixed)
#define NB 16
#define NM 128
#define NH 256
#define NE 128
#define NC 384
#define NROWS 2048
#define EDGE_GRID 148

// Scratch
__device__ float g_msgE[NROWS * NE];
// chunk-blocked fp16 operands: [kc][n=256][k=64], each 32KB chunk contiguous
__device__ half  g_WrB[6 * 256 * 64];
__device__ half  g_W0B[4 * 256 * 64];
__device__ half  g_W1B[4 * 256 * 64];
__device__ half  g_XB[NB * 2 * 256 * 64];

// ---------------------------------------------------------------------------
// helpers
// ---------------------------------------------------------------------------
__device__ __forceinline__ uint32_t h2u(half2 h) {
    return *reinterpret_cast<uint32_t*>(&h);
}
__device__ __forceinline__ uint2 f4toh4(float4 v) {
    return make_uint2(h2u(__floats2half2_rn(v.x, v.y)),
                      h2u(__floats2half2_rn(v.z, v.w)));
}
__device__ __forceinline__ void mma16h(float* d, const uint32_t* a, const uint32_t* b) {
    asm volatile(
        "mma.sync.aligned.m16n8k16.row.col.f32.f16.f16.f32 "
        "{%0,%1,%2,%3}, {%4,%5,%6,%7}, {%8,%9}, {%0,%1,%2,%3};"
        : "+f"(d[0]), "+f"(d[1]), "+f"(d[2]), "+f"(d[3])
        : "r"(a[0]), "r"(a[1]), "r"(a[2]), "r"(a[3]),
          "r"(b[0]), "r"(b[1]));
}

// ---------------------------------------------------------------------------
// cvt kernel: W (row-major [K][256]) / X_b ([128][256]) -> blocked fp16
//   out[(kc*256 + n)*64 + kl] = src[(kc*64+kl)*256 + n]
// grid 368: [0,48) Wr, [48,80) W0, [80,112) W1, [112,368) X.
// ---------------------------------------------------------------------------
__global__ __launch_bounds__(256)
void cvt_blocked(const float* __restrict__ Wr, const float* __restrict__ W0,
                 const float* __restrict__ W1, const float* __restrict__ X)
{
    __shared__ float tile[64][33];
    const int id = blockIdx.x;
    const float* src; half* dst; int kc, n0;
    if (id < 48)       { kc = id >> 3; n0 = (id & 7) * 32; src = Wr; dst = g_WrB; }
    else if (id < 80)  { int t = id - 48; kc = t >> 3; n0 = (t & 7) * 32;
                         src = W0; dst = g_W0B; }
    else if (id < 112) { int t = id - 80; kc = t >> 3; n0 = (t & 7) * 32;
                         src = W1; dst = g_W1B; }
    else {
        int t = id - 112;              // b(16) x kc(2) x nt(8)
        int b = t >> 4, tt = t & 15;
        kc = tt >> 3; n0 = (tt & 7) * 32;
        src = X + (size_t)b * 32768;
        dst = g_XB + (size_t)b * 32768;
    }
    const int c = threadIdx.x & 31, r8 = threadIdx.x >> 5;
    #pragma unroll
    for (int p = 0; p < 8; ++p) {
        int r = r8 + p * 8;
        tile[r][c] = src[(size_t)(kc * 64 + r) * 256 + n0 + c];
    }
    __syncthreads();
    const int nl = threadIdx.x >> 3, kl0 = (threadIdx.x & 7) * 8;
    half* o = dst + ((size_t)(kc * 256 + n0 + nl) * 64 + kl0);
    uint4 v;
    v.x = h2u(__floats2half2_rn(tile[kl0 + 0][nl], tile[kl0 + 1][nl]));
    v.y = h2u(__floats2half2_rn(tile[kl0 + 2][nl], tile[kl0 + 3][nl]));
    v.z = h2u(__floats2half2_rn(tile[kl0 + 4][nl], tile[kl0 + 5][nl]));
    v.w = h2u(__floats2half2_rn(tile[kl0 + 6][nl], tile[kl0 + 7][nl]));
    *(uint4*)o = v;
}

// ---------------------------------------------------------------------------
// Edge kernel (VERBATIM R11 — proven 86.5 config): fp16 mma, scalar frag
// loads, 512 thr = 16 warps (4 rg x 4 cg), persistent, stage->LDG->sync->mma.
// ---------------------------------------------------------------------------
#define EH_PITCH 136
#define ES_OFF   0
#define WS_OFF   34816
#define AW_OFF   69632
#define RED_OFF  70656
#define SM_BYTES 72192

__device__ __forceinline__ void compute_quarter_h(const half* __restrict__ ap,
                                                  const half* __restrict__ bp,
                                                  float acc[2][4][4])
{
    #pragma unroll
    for (int ss = 0; ss < 2; ++ss) {
        const int kb = ss * 16;
        uint32_t a[2][4];
        #pragma unroll
        for (int m = 0; m < 2; ++m) {
            const half* p = ap + m * (16 * EH_PITCH) + kb;
            a[m][0] = *(const uint32_t*)(p);
            a[m][1] = *(const uint32_t*)(p + 8 * EH_PITCH);
            a[m][2] = *(const uint32_t*)(p + 8);
            a[m][3] = *(const uint32_t*)(p + 8 * EH_PITCH + 8);
        }
        uint32_t bq[4][2];
        #pragma unroll
        for (int n = 0; n < 4; ++n) {
            const half* p = bp + n * (8 * EH_PITCH) + kb;
            bq[n][0] = *(const uint32_t*)(p);
            bq[n][1] = *(const uint32_t*)(p + 8);
        }
        #pragma unroll
        for (int m = 0; m < 2; ++m)
            #pragma unroll
            for (int n = 0; n < 4; ++n)
                mma16h(acc[m][n], a[m], bq[n]);
    }
}

__global__ __launch_bounds__(512, 1)
void edge_msg_mma(const float* __restrict__ E,
                  const float* __restrict__ A,
                  const float* __restrict__ We,
                  const float* __restrict__ be,
                  float* __restrict__ msgE)
{
    extern __shared__ char smc[];
    half*  Es  = (half*)(smc + ES_OFF);
    half*  Ws  = (half*)(smc + WS_OFF);
    float* awb = (float*)(smc + AW_OFF);
    float* red = (float*)(smc + RED_OFF);

    const int tid  = threadIdx.x;
    const int lane = tid & 31;
    const int wid  = tid >> 5;
    const int rg   = wid >> 2;
    const int cg   = wid & 3;
    const int row0 = rg * 32;
    const int col0 = cg * 32;

    float be0[4], be1[4];
    #pragma unroll
    for (int n = 0; n < 4; ++n) {
        be0[n] = be[col0 + 8 * n + 2 * (lane & 3)];
        be1[n] = be[col0 + 8 * n + 2 * (lane & 3) + 1];
    }

    for (int idx = tid; idx < 8192; idx += 512) {
        int f = idx & 127;
        int e = (idx >> 7) * 2;
        *(half2*)(Ws + f * EH_PITCH + e) =
            __floats2half2_rn(We[(size_t)e * 128 + f], We[(size_t)(e + 1) * 128 + f]);
    }

    const int t0  = blockIdx.x;
    const int ntl = (NROWS - t0 + EDGE_GRID - 1) / EDGE_GRID;

    const int ech = (tid & 7) * 4;
    const int ir0 = tid >> 3;
    auto ldq = [&](float4* r, int t, int q) {
        const float* src = E + (size_t)(t >> 7) * 2097152
                             + (size_t)ir0 * 16384
                             + (size_t)(t & 127) * 128 + q * 32 + ech;
        r[0] = *(const float4*)(src);
        r[1] = *(const float4*)(src + (size_t)64 * 16384);
    };
    half* qdst0 = Es + ir0 * EH_PITCH + ech;

    float4 pre[2];
    ldq(pre, t0, 0);
    float awreg = (tid < 128)
        ? A[(size_t)(t0 >> 7) * 16384 + (size_t)tid * 128 + (t0 & 127)] : 0.f;

    float acc[2][4][4];
    #pragma unroll
    for (int m = 0; m < 2; ++m)
        #pragma unroll
        for (int n = 0; n < 4; ++n)
            #pragma unroll
            for (int q = 0; q < 4; ++q) acc[m][n][q] = 0.f;

    const half* aptr = Es + (row0 + (lane >> 2)) * EH_PITCH + (lane & 3) * 2;
    const half* bptr = Ws + (col0 + (lane >> 2)) * EH_PITCH + (lane & 3) * 2;

    for (int k = 0; k < ntl; ++k) {
        const int t = t0 + k * EDGE_GRID;
        const bool hn = (k + 1 < ntl);

        #pragma unroll
        for (int q = 0; q < 4; ++q) {
            half* qd = qdst0 + q * 32;
            {
                half2 h0 = __floats2half2_rn(pre[0].x, pre[0].y);
                half2 h1 = __floats2half2_rn(pre[0].z, pre[0].w);
                *(uint2*)(qd) = make_uint2(h2u(h0), h2u(h1));
                half2 h2 = __floats2half2_rn(pre[1].x, pre[1].y);
                half2 h3 = __floats2half2_rn(pre[1].z, pre[1].w);
                *(uint2*)(qd + 64 * EH_PITCH) = make_uint2(h2u(h2), h2u(h3));
            }
            if (q == 0 && tid < 128) {
                awb[(k & 1) * 128 + tid] = awreg;
                if (hn) {
                    const int tn = t + EDGE_GRID;
                    awreg = A[(size_t)(tn >> 7) * 16384 + (size_t)tid * 128 + (tn & 127)];
                }
            }
            if (q < 3)       ldq(pre, t, q + 1);
            else if (hn)     ldq(pre, t + EDGE_GRID, 0);

            __syncthreads();
            compute_quarter_h(aptr + q * 32, bptr + q * 32, acc);
        }

        // ---- epilogue ----
        {
            const float* aw = awb + (k & 1) * 128;
            float p0[4], p1[4];
            #pragma unroll
            for (int n = 0; n < 4; ++n) { p0[n] = 0.f; p1[n] = 0.f; }
            #pragma unroll
            for (int m = 0; m < 2; ++m) {
                float w0 = aw[row0 + 16 * m + (lane >> 2)];
                float w1 = aw[row0 + 16 * m + (lane >> 2) + 8];
                #pragma unroll
                for (int n = 0; n < 4; ++n) {
                    p0[n] += w0 * fmaxf(acc[m][n][0] + be0[n], 0.f)
                           + w1 * fmaxf(acc[m][n][2] + be0[n], 0.f);
                    p1[n] += w0 * fmaxf(acc[m][n][1] + be1[n], 0.f)
                           + w1 * fmaxf(acc[m][n][3] + be1[n], 0.f);
                    acc[m][n][0] = 0.f; acc[m][n][1] = 0.f;
                    acc[m][n][2] = 0.f; acc[m][n][3] = 0.f;
                }
            }
            #pragma unroll
            for (int off = 4; off < 32; off <<= 1) {
                #pragma unroll
                for (int n = 0; n < 4; ++n) {
                    p0[n] += __shfl_xor_sync(0xffffffffu, p0[n], off);
                    p1[n] += __shfl_xor_sync(0xffffffffu, p1[n], off);
                }
            }
            if (rg > 0 && lane < 4) {
                #pragma unroll
                for (int n = 0; n < 4; ++n) {
                    int f = col0 + 8 * n + 2 * lane;
                    red[(rg - 1) * 128 + f]     = p0[n];
                    red[(rg - 1) * 128 + f + 1] = p1[n];
                }
            }
            __syncthreads();
            if (rg == 0 && lane < 4) {
                #pragma unroll
                for (int n = 0; n < 4; ++n) {
                    int f = col0 + 8 * n + 2 * lane;
                    msgE[(size_t)t * NE + f] =
                        p0[n] + red[f] + red[128 + f] + red[256 + f];
                    msgE[(size_t)t * NE + f + 1] =
                        p1[n] + red[f + 1] + red[128 + f + 1] + red[256 + f + 1];
                }
            }
        }
    }
}

// ---------------------------------------------------------------------------
// Fused MLP + msg_x (R12 version): fp16 mma, scalar frag loads, 64-wide
// k-chunks from blocked global. One CTA = 16 rows. grid 128, 8 warps.
// ---------------------------------------------------------------------------
#define AM_P  392
#define AST_P 136
#define FT_P  264
#define BS_P  72
#define OFF_AM  0
#define OFF_AST 12544
#define OFF_TS  16896
#define OFF_US  25344
#define OFF_BS0 33792
#define OFF_BS1 70656
#define FSM_BYTES 107520

__device__ __forceinline__ void fgemm_h(const half* __restrict__ Asm, int PA,
                                        const half* __restrict__ WB,
                                        half* __restrict__ bs0,
                                        half* __restrict__ bs1,
                                        int nch, int tid, int lane, int wcol0,
                                        float acc[4][4])
{
    const half* wsrc = WB + (size_t)tid * 64;
    uint4 pw[8];
    #pragma unroll
    for (int q = 0; q < 8; ++q) pw[q] = *(const uint4*)(wsrc + q * 8);

    const half* apb = Asm + (lane >> 2) * PA + (lane & 3) * 2;

    for (int kc = 0; kc < nch; ++kc) {
        half* bd = ((kc & 1) ? bs1 : bs0) + tid * BS_P;
        #pragma unroll
        for (int q = 0; q < 8; ++q) *(uint4*)(bd + q * 8) = pw[q];
        if (kc + 1 < nch) {
            const half* ws = wsrc + (size_t)(kc + 1) * 16384;
            #pragma unroll
            for (int q = 0; q < 8; ++q) pw[q] = *(const uint4*)(ws + q * 8);
        }
        __syncthreads();

        const half* bp = ((kc & 1) ? bs1 : bs0)
                       + (wcol0 + (lane >> 2)) * BS_P + (lane & 3) * 2;
        const half* ap = apb + kc * 64;
        #pragma unroll
        for (int ss = 0; ss < 4; ++ss) {
            const half* pa = ap + ss * 16;
            uint32_t a[4];
            a[0] = *(const uint32_t*)(pa);
            a[1] = *(const uint32_t*)(pa + 8 * PA);
            a[2] = *(const uint32_t*)(pa + 8);
            a[3] = *(const uint32_t*)(pa + 8 * PA + 8);
            uint32_t bq[4][2];
            #pragma unroll
            for (int n = 0; n < 4; ++n) {
                const half* pb = bp + n * (8 * BS_P) + ss * 16;
                bq[n][0] = *(const uint32_t*)(pb);
                bq[n][1] = *(const uint32_t*)(pb + 8);
            }
            #pragma unroll
            for (int n = 0; n < 4; ++n) mma16h(acc[n], a, bq[n]);
        }
    }
}

__global__ __launch_bounds__(256)
void mlp_fused(const float* __restrict__ msgE,
               const float* __restrict__ X,
               const float* __restrict__ A,
               const float* __restrict__ epsp,
               const float* __restrict__ br, const float* __restrict__ b0,
               const float* __restrict__ b1,
               float* __restrict__ Out)
{
    extern __shared__ char fsc[];
    half* Am  = (half*)(fsc + OFF_AM);
    half* AsT = (half*)(fsc + OFF_AST);
    half* Ts  = (half*)(fsc + OFF_TS);
    half* Us  = (half*)(fsc + OFF_US);
    half* Bs0 = (half*)(fsc + OFF_BS0);
    half* Bs1 = (half*)(fsc + OFF_BS1);

    const int r0   = blockIdx.x * 16;
    const int b    = r0 >> 7;
    const int j0   = r0 & 127;
    const int tid  = threadIdx.x;
    const int lane = tid & 31;
    const int wid  = tid >> 5;
    const int wcol0 = wid * 32;

    for (int idx = tid; idx < 2048; idx += 256) {
        int i = idx >> 4, jj = idx & 15;
        AsT[jj * AST_P + i] =
            __float2half(A[(size_t)b * 16384 + (size_t)i * 128 + j0 + jj]);
    }
    {
        const int row = tid >> 4;
        const int c   = (tid & 15) * 8;
        const float* src = msgE + (size_t)(r0 + row) * NE + c;
        half* dst = Am + row * AM_P + 256 + c;
        *(uint2*)(dst)     = f4toh4(*(const float4*)(src));
        *(uint2*)(dst + 4) = f4toh4(*(const float4*)(src + 4));
    }
    __syncthreads();

    float acc[4][4];
    #pragma unroll
    for (int n = 0; n < 4; ++n)
        #pragma unroll
        for (int q = 0; q < 4; ++q) acc[n][q] = 0.f;

    const int erow = lane >> 2;
    const int ecol = 2 * (lane & 3);

    // ---- msg_x = AsT @ X_b -> Am cols 0..255 ----
    fgemm_h(AsT, AST_P, g_XB + (size_t)b * 32768, Bs0, Bs1,
            2, tid, lane, wcol0, acc);
    #pragma unroll
    for (int n = 0; n < 4; ++n) {
        int col = wcol0 + 8 * n + ecol;
        *(uint32_t*)(Am + erow * AM_P + col) =
            h2u(__floats2half2_rn(acc[n][0], acc[n][1]));
        *(uint32_t*)(Am + (erow + 8) * AM_P + col) =
            h2u(__floats2half2_rn(acc[n][2], acc[n][3]));
        acc[n][0] = acc[n][1] = acc[n][2] = acc[n][3] = 0.f;
    }
    __syncthreads();

    // ---- layer 1: t = (1+eps)*X + relu(Am@Wr + br) ----
    fgemm_h(Am, AM_P, g_WrB, Bs0, Bs1, 6, tid, lane, wcol0, acc);
    {
        const float epsv = 1.f + *epsp;
        #pragma unroll
        for (int n = 0; n < 4; ++n) {
            int col = wcol0 + 8 * n + ecol;
            float v00 = fmaxf(acc[n][0] + br[col], 0.f)
                      + epsv * X[(size_t)(r0 + erow) * 256 + col];
            float v01 = fmaxf(acc[n][1] + br[col + 1], 0.f)
                      + epsv * X[(size_t)(r0 + erow) * 256 + col + 1];
            float v10 = fmaxf(acc[n][2] + br[col], 0.f)
                      + epsv * X[(size_t)(r0 + erow + 8) * 256 + col];
            float v11 = fmaxf(acc[n][3] + br[col + 1], 0.f)
                      + epsv * X[(size_t)(r0 + erow + 8) * 256 + col + 1];
            *(uint32_t*)(Ts + erow * FT_P + col)       = h2u(__floats2half2_rn(v00, v01));
            *(uint32_t*)(Ts + (erow + 8) * FT_P + col) = h2u(__floats2half2_rn(v10, v11));
            acc[n][0] = acc[n][1] = acc[n][2] = acc[n][3] = 0.f;
        }
    }
    __syncthreads();

    // ---- layer 2: u = relu(t@W0 + b0) ----
    fgemm_h(Ts, FT_P, g_W0B, Bs0, Bs1, 4, tid, lane, wcol0, acc);
    #pragma unroll
    for (int n = 0; n < 4; ++n) {
        int col = wcol0 + 8 * n + ecol;
        *(uint32_t*)(Us + erow * FT_P + col) = h2u(__floats2half2_rn(
            fmaxf(acc[n][0] + b0[col], 0.f), fmaxf(acc[n][1] + b0[col + 1], 0.f)));
        *(uint32_t*)(Us + (erow + 8) * FT_P + col) = h2u(__floats2half2_rn(
            fmaxf(acc[n][2] + b0[col], 0.f), fmaxf(acc[n][3] + b0[col + 1], 0.f)));
        acc[n][0] = acc[n][1] = acc[n][2] = acc[n][3] = 0.f;
    }
    __syncthreads();

    // ---- layer 3: out = relu(u@W1 + b1) ----
    fgemm_h(Us, FT_P, g_W1B, Bs0, Bs1, 4, tid, lane, wcol0, acc);
    #pragma unroll
    for (int n = 0; n < 4; ++n) {
        int col = wcol0 + 8 * n + ecol;
        float2 v0 = make_float2(fmaxf(acc[n][0] + b1[col], 0.f),
                                fmaxf(acc[n][1] + b1[col + 1], 0.f));
        float2 v1 = make_float2(fmaxf(acc[n][2] + b1[col], 0.f),
                                fmaxf(acc[n][3] + b1[col + 1], 0.f));
        *(float2*)(Out + (size_t)(r0 + erow) * 256 + col)     = v0;
        *(float2*)(Out + (size_t)(r0 + erow + 8) * 256 + col) = v1;
    }
}

// ---------------------------------------------------------------------------
extern "C" void kernel_launch(void* const* d_in, const int* in_sizes, int n_in,
                              void* d_out, int out_size)
{
    const float* X   = (const float*)d_in[0];
    const float* E   = (const float*)d_in[1];
    const float* A   = (const float*)d_in[2];
    const float* eps = (const float*)d_in[3];
    const float* We  = (const float*)d_in[4];
    const float* be  = (const float*)d_in[5];
    const float* Wr  = (const float*)d_in[6];
    const float* br  = (const float*)d_in[7];
    const float* W0  = (const float*)d_in[8];
    const float* b0  = (const float*)d_in[9];
    const float* W1  = (const float*)d_in[10];
    const float* b1  = (const float*)d_in[11];
    float* out = (float*)d_out;

    void* pmsg;
    cudaGetSymbolAddress(&pmsg, g_msgE);
    float* msgE = (float*)pmsg;

    cudaFuncSetAttribute(edge_msg_mma,
                         cudaFuncAttributeMaxDynamicSharedMemorySize, SM_BYTES);
    cudaFuncSetAttribute(mlp_fused,
                         cudaFuncAttributeMaxDynamicSharedMemorySize, FSM_BYTES);

    cvt_blocked<<<368, 256>>>(Wr, W0, W1, X);
    edge_msg_mma<<<EDGE_GRID, 512, SM_BYTES>>>(E, A, We, be, msgE);
    mlp_fused<<<128, 256, FSM_BYTES>>>(msgE, X, A, eps, br, b0, b1, out);
}

// round 14
// speedup vs baseline: 1.2190x; 1.1264x over previous
#include <cuda_runtime.h>
#include <cuda_fp16.h>
#include <cstdint>
#include <cstddef>

// Shapes (fixed)
#define NB 16
#define NM 128
#define NH 256
#define NE 128
#define NC 384
#define NROWS 2048
#define EDGE_GRID 148

// Scratch
__device__ float g_msgE[NROWS * NE];
// chunk-blocked fp16 operands: [kc][n=256][k=32], each 16KB chunk contiguous
__device__ half  g_WrB[12 * 256 * 32];
__device__ half  g_W0B[8 * 256 * 32];
__device__ half  g_W1B[8 * 256 * 32];
__device__ half  g_XB[NB * 4 * 256 * 32];

// ---------------------------------------------------------------------------
// helpers
// ---------------------------------------------------------------------------
__device__ __forceinline__ uint32_t h2u(half2 h) {
    return *reinterpret_cast<uint32_t*>(&h);
}
__device__ __forceinline__ uint2 f4toh4(float4 v) {
    return make_uint2(h2u(__floats2half2_rn(v.x, v.y)),
                      h2u(__floats2half2_rn(v.z, v.w)));
}
__device__ __forceinline__ void mma16h(float* d, const uint32_t* a, const uint32_t* b) {
    asm volatile(
        "mma.sync.aligned.m16n8k16.row.col.f32.f16.f16.f32 "
        "{%0,%1,%2,%3}, {%4,%5,%6,%7}, {%8,%9}, {%0,%1,%2,%3};"
        : "+f"(d[0]), "+f"(d[1]), "+f"(d[2]), "+f"(d[3])
        : "r"(a[0]), "r"(a[1]), "r"(a[2]), "r"(a[3]),
          "r"(b[0]), "r"(b[1]));
}

// ---------------------------------------------------------------------------
// cvt kernel (VERBATIM R11): W / X_b -> blocked fp16 [kc][256][32]
// ---------------------------------------------------------------------------
__global__ __launch_bounds__(256)
void cvt_blocked(const float* __restrict__ Wr, const float* __restrict__ W0,
                 const float* __restrict__ W1, const float* __restrict__ X)
{
    __shared__ float tile[32][33];
    const int id = blockIdx.x;
    const float* src; half* dst; int kc, n0;
    if (id < 96)       { kc = id >> 3; n0 = (id & 7) * 32; src = Wr; dst = g_WrB; }
    else if (id < 160) { int t = id - 96;  kc = t >> 3; n0 = (t & 7) * 32;
                         src = W0; dst = g_W0B; }
    else if (id < 224) { int t = id - 160; kc = t >> 3; n0 = (t & 7) * 32;
                         src = W1; dst = g_W1B; }
    else {
        int t = id - 224;
        int b = t >> 5, tt = t & 31;
        kc = tt >> 3; n0 = (tt & 7) * 32;
        src = X + (size_t)b * 32768;
        dst = g_XB + (size_t)b * 32768;
    }
    const int c = threadIdx.x & 31, r8 = threadIdx.x >> 5;
    #pragma unroll
    for (int p = 0; p < 4; ++p) {
        int r = r8 + p * 8;
        tile[r][c] = src[(size_t)(kc * 32 + r) * 256 + n0 + c];
    }
    __syncthreads();
    const int nl = threadIdx.x >> 3, kl0 = (threadIdx.x & 7) * 4;
    half* o = dst + ((size_t)(kc * 256 + n0 + nl) * 32 + kl0);
    half2 h0 = __floats2half2_rn(tile[kl0][nl],     tile[kl0 + 1][nl]);
    half2 h1 = __floats2half2_rn(tile[kl0 + 2][nl], tile[kl0 + 3][nl]);
    *(uint2*)o = make_uint2(h2u(h0), h2u(h1));
}

// ---------------------------------------------------------------------------
// Edge kernel (VERBATIM R11 — proven 86.5 config)
// ---------------------------------------------------------------------------
#define EH_PITCH 136
#define ES_OFF   0
#define WS_OFF   34816
#define AW_OFF   69632
#define RED_OFF  70656
#define SM_BYTES 72192

__device__ __forceinline__ void compute_quarter_h(const half* __restrict__ ap,
                                                  const half* __restrict__ bp,
                                                  float acc[2][4][4])
{
    #pragma unroll
    for (int ss = 0; ss < 2; ++ss) {
        const int kb = ss * 16;
        uint32_t a[2][4];
        #pragma unroll
        for (int m = 0; m < 2; ++m) {
            const half* p = ap + m * (16 * EH_PITCH) + kb;
            a[m][0] = *(const uint32_t*)(p);
            a[m][1] = *(const uint32_t*)(p + 8 * EH_PITCH);
            a[m][2] = *(const uint32_t*)(p + 8);
            a[m][3] = *(const uint32_t*)(p + 8 * EH_PITCH + 8);
        }
        uint32_t bq[4][2];
        #pragma unroll
        for (int n = 0; n < 4; ++n) {
            const half* p = bp + n * (8 * EH_PITCH) + kb;
            bq[n][0] = *(const uint32_t*)(p);
            bq[n][1] = *(const uint32_t*)(p + 8);
        }
        #pragma unroll
        for (int m = 0; m < 2; ++m)
            #pragma unroll
            for (int n = 0; n < 4; ++n)
                mma16h(acc[m][n], a[m], bq[n]);
    }
}

__global__ __launch_bounds__(512, 1)
void edge_msg_mma(const float* __restrict__ E,
                  const float* __restrict__ A,
                  const float* __restrict__ We,
                  const float* __restrict__ be,
                  float* __restrict__ msgE)
{
    extern __shared__ char smc[];
    half*  Es  = (half*)(smc + ES_OFF);
    half*  Ws  = (half*)(smc + WS_OFF);
    float* awb = (float*)(smc + AW_OFF);
    float* red = (float*)(smc + RED_OFF);

    const int tid  = threadIdx.x;
    const int lane = tid & 31;
    const int wid  = tid >> 5;
    const int rg   = wid >> 2;
    const int cg   = wid & 3;
    const int row0 = rg * 32;
    const int col0 = cg * 32;

    float be0[4], be1[4];
    #pragma unroll
    for (int n = 0; n < 4; ++n) {
        be0[n] = be[col0 + 8 * n + 2 * (lane & 3)];
        be1[n] = be[col0 + 8 * n + 2 * (lane & 3) + 1];
    }

    for (int idx = tid; idx < 8192; idx += 512) {
        int f = idx & 127;
        int e = (idx >> 7) * 2;
        *(half2*)(Ws + f * EH_PITCH + e) =
            __floats2half2_rn(We[(size_t)e * 128 + f], We[(size_t)(e + 1) * 128 + f]);
    }

    const int t0  = blockIdx.x;
    const int ntl = (NROWS - t0 + EDGE_GRID - 1) / EDGE_GRID;

    const int ech = (tid & 7) * 4;
    const int ir0 = tid >> 3;
    auto ldq = [&](float4* r, int t, int q) {
        const float* src = E + (size_t)(t >> 7) * 2097152
                             + (size_t)ir0 * 16384
                             + (size_t)(t & 127) * 128 + q * 32 + ech;
        r[0] = *(const float4*)(src);
        r[1] = *(const float4*)(src + (size_t)64 * 16384);
    };
    half* qdst0 = Es + ir0 * EH_PITCH + ech;

    float4 pre[2];
    ldq(pre, t0, 0);
    float awreg = (tid < 128)
        ? A[(size_t)(t0 >> 7) * 16384 + (size_t)tid * 128 + (t0 & 127)] : 0.f;

    float acc[2][4][4];
    #pragma unroll
    for (int m = 0; m < 2; ++m)
        #pragma unroll
        for (int n = 0; n < 4; ++n)
            #pragma unroll
            for (int q = 0; q < 4; ++q) acc[m][n][q] = 0.f;

    const half* aptr = Es + (row0 + (lane >> 2)) * EH_PITCH + (lane & 3) * 2;
    const half* bptr = Ws + (col0 + (lane >> 2)) * EH_PITCH + (lane & 3) * 2;

    for (int k = 0; k < ntl; ++k) {
        const int t = t0 + k * EDGE_GRID;
        const bool hn = (k + 1 < ntl);

        #pragma unroll
        for (int q = 0; q < 4; ++q) {
            half* qd = qdst0 + q * 32;
            {
                half2 h0 = __floats2half2_rn(pre[0].x, pre[0].y);
                half2 h1 = __floats2half2_rn(pre[0].z, pre[0].w);
                *(uint2*)(qd) = make_uint2(h2u(h0), h2u(h1));
                half2 h2 = __floats2half2_rn(pre[1].x, pre[1].y);
                half2 h3 = __floats2half2_rn(pre[1].z, pre[1].w);
                *(uint2*)(qd + 64 * EH_PITCH) = make_uint2(h2u(h2), h2u(h3));
            }
            if (q == 0 && tid < 128) {
                awb[(k & 1) * 128 + tid] = awreg;
                if (hn) {
                    const int tn = t + EDGE_GRID;
                    awreg = A[(size_t)(tn >> 7) * 16384 + (size_t)tid * 128 + (tn & 127)];
                }
            }
            if (q < 3)       ldq(pre, t, q + 1);
            else if (hn)     ldq(pre, t + EDGE_GRID, 0);

            __syncthreads();
            compute_quarter_h(aptr + q * 32, bptr + q * 32, acc);
        }

        // ---- epilogue ----
        {
            const float* aw = awb + (k & 1) * 128;
            float p0[4], p1[4];
            #pragma unroll
            for (int n = 0; n < 4; ++n) { p0[n] = 0.f; p1[n] = 0.f; }
            #pragma unroll
            for (int m = 0; m < 2; ++m) {
                float w0 = aw[row0 + 16 * m + (lane >> 2)];
                float w1 = aw[row0 + 16 * m + (lane >> 2) + 8];
                #pragma unroll
                for (int n = 0; n < 4; ++n) {
                    p0[n] += w0 * fmaxf(acc[m][n][0] + be0[n], 0.f)
                           + w1 * fmaxf(acc[m][n][2] + be0[n], 0.f);
                    p1[n] += w0 * fmaxf(acc[m][n][1] + be1[n], 0.f)
                           + w1 * fmaxf(acc[m][n][3] + be1[n], 0.f);
                    acc[m][n][0] = 0.f; acc[m][n][1] = 0.f;
                    acc[m][n][2] = 0.f; acc[m][n][3] = 0.f;
                }
            }
            #pragma unroll
            for (int off = 4; off < 32; off <<= 1) {
                #pragma unroll
                for (int n = 0; n < 4; ++n) {
                    p0[n] += __shfl_xor_sync(0xffffffffu, p0[n], off);
                    p1[n] += __shfl_xor_sync(0xffffffffu, p1[n], off);
                }
            }
            if (rg > 0 && lane < 4) {
                #pragma unroll
                for (int n = 0; n < 4; ++n) {
                    int f = col0 + 8 * n + 2 * lane;
                    red[(rg - 1) * 128 + f]     = p0[n];
                    red[(rg - 1) * 128 + f + 1] = p1[n];
                }
            }
            __syncthreads();
            if (rg == 0 && lane < 4) {
                #pragma unroll
                for (int n = 0; n < 4; ++n) {
                    int f = col0 + 8 * n + 2 * lane;
                    msgE[(size_t)t * NE + f] =
                        p0[n] + red[f] + red[128 + f] + red[256 + f];
                    msgE[(size_t)t * NE + f + 1] =
                        p1[n] + red[f + 1] + red[128 + f + 1] + red[256 + f + 1];
                }
            }
        }
    }
}

// ---------------------------------------------------------------------------
// Fused MLP + msg_x (R11 layout/pitches; ONE change: depth-2 weight prefetch)
// One CTA = 16 rows. grid 128, 256 threads = 8 warps, warp tile 16x32.
// ---------------------------------------------------------------------------
#define AM_P  392
#define AST_P 136
#define FT_P  264
#define BS_P  40
#define OFF_AM  0
#define OFF_AST 12544
#define OFF_TS  16896
#define OFF_US  25344
#define OFF_BS0 33792
#define OFF_BS1 54272
#define FSM_BYTES 74752

// WB: blocked [nch][256][32]; depth-2 register prefetch pipeline.
// Buffer-reuse proof: store(kc) follows sync(kc-1); every warp reached
// sync(kc-1) only after compute(kc-2) on buf[kc&1]. Safe.
__device__ __forceinline__ void fgemm_h(const half* __restrict__ Asm, int PA,
                                        const half* __restrict__ WB,
                                        half* __restrict__ bs0,
                                        half* __restrict__ bs1,
                                        int nch, int tid, int lane, int wcol0,
                                        float acc[4][4])
{
    const half* wsrc = WB + (size_t)tid * 32;
    uint4 pw0[4], pw1[4];
    #pragma unroll
    for (int q = 0; q < 4; ++q) pw0[q] = *(const uint4*)(wsrc + q * 8);
    if (nch > 1) {
        #pragma unroll
        for (int q = 0; q < 4; ++q) pw1[q] = *(const uint4*)(wsrc + 8192 + q * 8);
    }

    const half* apb = Asm + (lane >> 2) * PA + (lane & 3) * 2;

    for (int kc = 0; kc < nch; ++kc) {
        half* bd = ((kc & 1) ? bs1 : bs0) + tid * BS_P;
        #pragma unroll
        for (int q = 0; q < 4; ++q) *(uint4*)(bd + q * 8) = pw0[q];
        #pragma unroll
        for (int q = 0; q < 4; ++q) pw0[q] = pw1[q];
        if (kc + 2 < nch) {
            const half* ws = wsrc + (size_t)(kc + 2) * 8192;
            #pragma unroll
            for (int q = 0; q < 4; ++q) pw1[q] = *(const uint4*)(ws + q * 8);
        }
        __syncthreads();

        const half* bp = ((kc & 1) ? bs1 : bs0)
                       + (wcol0 + (lane >> 2)) * BS_P + (lane & 3) * 2;
        const half* ap = apb + kc * 32;
        #pragma unroll
        for (int ss = 0; ss < 2; ++ss) {
            const half* pa = ap + ss * 16;
            uint32_t a[4];
            a[0] = *(const uint32_t*)(pa);
            a[1] = *(const uint32_t*)(pa + 8 * PA);
            a[2] = *(const uint32_t*)(pa + 8);
            a[3] = *(const uint32_t*)(pa + 8 * PA + 8);
            uint32_t bq[4][2];
            #pragma unroll
            for (int n = 0; n < 4; ++n) {
                const half* pb = bp + n * (8 * BS_P) + ss * 16;
                bq[n][0] = *(const uint32_t*)(pb);
                bq[n][1] = *(const uint32_t*)(pb + 8);
            }
            #pragma unroll
            for (int n = 0; n < 4; ++n) mma16h(acc[n], a, bq[n]);
        }
    }
}

__global__ __launch_bounds__(256)
void mlp_fused(const float* __restrict__ msgE,
               const float* __restrict__ X,
               const float* __restrict__ A,
               const float* __restrict__ epsp,
               const float* __restrict__ br, const float* __restrict__ b0,
               const float* __restrict__ b1,
               float* __restrict__ Out)
{
    extern __shared__ char fsc[];
    half* Am  = (half*)(fsc + OFF_AM);
    half* AsT = (half*)(fsc + OFF_AST);
    half* Ts  = (half*)(fsc + OFF_TS);
    half* Us  = (half*)(fsc + OFF_US);
    half* Bs0 = (half*)(fsc + OFF_BS0);
    half* Bs1 = (half*)(fsc + OFF_BS1);

    const int r0   = blockIdx.x * 16;
    const int b    = r0 >> 7;
    const int j0   = r0 & 127;
    const int tid  = threadIdx.x;
    const int lane = tid & 31;
    const int wid  = tid >> 5;
    const int wcol0 = wid * 32;

    for (int idx = tid; idx < 2048; idx += 256) {
        int i = idx >> 4, jj = idx & 15;
        AsT[jj * AST_P + i] =
            __float2half(A[(size_t)b * 16384 + (size_t)i * 128 + j0 + jj]);
    }
    {
        const int row = tid >> 4;
        const int c   = (tid & 15) * 8;
        const float* src = msgE + (size_t)(r0 + row) * NE + c;
        half* dst = Am + row * AM_P + 256 + c;
        *(uint2*)(dst)     = f4toh4(*(const float4*)(src));
        *(uint2*)(dst + 4) = f4toh4(*(const float4*)(src + 4));
    }
    __syncthreads();

    float acc[4][4];
    #pragma unroll
    for (int n = 0; n < 4; ++n)
        #pragma unroll
        for (int q = 0; q < 4; ++q) acc[n][q] = 0.f;

    const int erow = lane >> 2;
    const int ecol = 2 * (lane & 3);

    // ---- msg_x = AsT @ X_b -> Am cols 0..255 ----
    fgemm_h(AsT, AST_P, g_XB + (size_t)b * 32768, Bs0, Bs1,
            4, tid, lane, wcol0, acc);
    #pragma unroll
    for (int n = 0; n < 4; ++n) {
        int col = wcol0 + 8 * n + ecol;
        *(uint32_t*)(Am + erow * AM_P + col) =
            h2u(__floats2half2_rn(acc[n][0], acc[n][1]));
        *(uint32_t*)(Am + (erow + 8) * AM_P + col) =
            h2u(__floats2half2_rn(acc[n][2], acc[n][3]));
        acc[n][0] = acc[n][1] = acc[n][2] = acc[n][3] = 0.f;
    }
    __syncthreads();

    // ---- layer 1: t = (1+eps)*X + relu(Am@Wr + br) ----
    fgemm_h(Am, AM_P, g_WrB, Bs0, Bs1, 12, tid, lane, wcol0, acc);
    {
        const float epsv = 1.f + *epsp;
        #pragma unroll
        for (int n = 0; n < 4; ++n) {
            int col = wcol0 + 8 * n + ecol;
            float v00 = fmaxf(acc[n][0] + br[col], 0.f)
                      + epsv * X[(size_t)(r0 + erow) * 256 + col];
            float v01 = fmaxf(acc[n][1] + br[col + 1], 0.f)
                      + epsv * X[(size_t)(r0 + erow) * 256 + col + 1];
            float v10 = fmaxf(acc[n][2] + br[col], 0.f)
                      + epsv * X[(size_t)(r0 + erow + 8) * 256 + col];
            float v11 = fmaxf(acc[n][3] + br[col + 1], 0.f)
                      + epsv * X[(size_t)(r0 + erow + 8) * 256 + col + 1];
            *(uint32_t*)(Ts + erow * FT_P + col)       = h2u(__floats2half2_rn(v00, v01));
            *(uint32_t*)(Ts + (erow + 8) * FT_P + col) = h2u(__floats2half2_rn(v10, v11));
            acc[n][0] = acc[n][1] = acc[n][2] = acc[n][3] = 0.f;
        }
    }
    __syncthreads();

    // ---- layer 2: u = relu(t@W0 + b0) ----
    fgemm_h(Ts, FT_P, g_W0B, Bs0, Bs1, 8, tid, lane, wcol0, acc);
    #pragma unroll
    for (int n = 0; n < 4; ++n) {
        int col = wcol0 + 8 * n + ecol;
        *(uint32_t*)(Us + erow * FT_P + col) = h2u(__floats2half2_rn(
            fmaxf(acc[n][0] + b0[col], 0.f), fmaxf(acc[n][1] + b0[col + 1], 0.f)));
        *(uint32_t*)(Us + (erow + 8) * FT_P + col) = h2u(__floats2half2_rn(
            fmaxf(acc[n][2] + b0[col], 0.f), fmaxf(acc[n][3] + b0[col + 1], 0.f)));
        acc[n][0] = acc[n][1] = acc[n][2] = acc[n][3] = 0.f;
    }
    __syncthreads();

    // ---- layer 3: out = relu(u@W1 + b1) ----
    fgemm_h(Us, FT_P, g_W1B, Bs0, Bs1, 8, tid, lane, wcol0, acc);
    #pragma unroll
    for (int n = 0; n < 4; ++n) {
        int col = wcol0 + 8 * n + ecol;
        float2 v0 = make_float2(fmaxf(acc[n][0] + b1[col], 0.f),
                                fmaxf(acc[n][1] + b1[col + 1], 0.f));
        float2 v1 = make_float2(fmaxf(acc[n][2] + b1[col], 0.f),
                                fmaxf(acc[n][3] + b1[col + 1], 0.f));
        *(float2*)(Out + (size_t)(r0 + erow) * 256 + col)     = v0;
        *(float2*)(Out + (size_t)(r0 + erow + 8) * 256 + col) = v1;
    }
}

// ---------------------------------------------------------------------------
extern "C" void kernel_launch(void* const* d_in, const int* in_sizes, int n_in,
                              void* d_out, int out_size)
{
    const float* X   = (const float*)d_in[0];
    const float* E   = (const float*)d_in[1];
    const float* A   = (const float*)d_in[2];
    const float* eps = (const float*)d_in[3];
    const float* We  = (const float*)d_in[4];
    const float* be  = (const float*)d_in[5];
    const float* Wr  = (const float*)d_in[6];
    const float* br  = (const float*)d_in[7];
    const float* W0  = (const float*)d_in[8];
    const float* b0  = (const float*)d_in[9];
    const float* W1  = (const float*)d_in[10];
    const float* b1  = (const float*)d_in[11];
    float* out = (float*)d_out;

    void* pmsg;
    cudaGetSymbolAddress(&pmsg, g_msgE);
    float* msgE = (float*)pmsg;

    cudaFuncSetAttribute(edge_msg_mma,
                         cudaFuncAttributeMaxDynamicSharedMemorySize, SM_BYTES);
    cudaFuncSetAttribute(mlp_fused,
                         cudaFuncAttributeMaxDynamicSharedMemorySize, FSM_BYTES);

    cvt_blocked<<<736, 256>>>(Wr, W0, W1, X);
    edge_msg_mma<<<EDGE_GRID, 512, SM_BYTES>>>(E, A, We, be, msgE);
    mlp_fused<<<128, 256, FSM_BYTES>>>(msgE, X, A, eps, br, b0, b1, out);
}

// round 15
// speedup vs baseline: 1.3174x; 1.0808x over previous
#include <cuda_runtime.h>
#include <cuda_fp16.h>
#include <cstdint>
#include <cstddef>

// Shapes (fixed)
#define NB 16
#define NM 128
#define NH 256
#define NE 128
#define NC 384
#define NROWS 2048
#define EDGE_GRID 148

// Scratch
__device__ float g_msgE[NROWS * NE];
// chunk-blocked fp16 operands: [kc][n=256][k=32], each 16KB chunk contiguous
__device__ half  g_WrB[12 * 256 * 32];
__device__ half  g_W0B[8 * 256 * 32];
__device__ half  g_W1B[8 * 256 * 32];
__device__ half  g_XB[NB * 4 * 256 * 32];

// ---------------------------------------------------------------------------
// helpers
// ---------------------------------------------------------------------------
__device__ __forceinline__ uint32_t h2u(half2 h) {
    return *reinterpret_cast<uint32_t*>(&h);
}
__device__ __forceinline__ uint2 f4toh4(float4 v) {
    return make_uint2(h2u(__floats2half2_rn(v.x, v.y)),
                      h2u(__floats2half2_rn(v.z, v.w)));
}
__device__ __forceinline__ void mma16h(float* d, const uint32_t* a, const uint32_t* b) {
    asm volatile(
        "mma.sync.aligned.m16n8k16.row.col.f32.f16.f16.f32 "
        "{%0,%1,%2,%3}, {%4,%5,%6,%7}, {%8,%9}, {%0,%1,%2,%3};"
        : "+f"(d[0]), "+f"(d[1]), "+f"(d[2]), "+f"(d[3])
        : "r"(a[0]), "r"(a[1]), "r"(a[2]), "r"(a[3]),
          "r"(b[0]), "r"(b[1]));
}

// ---------------------------------------------------------------------------
// cvt kernel (VERBATIM R14): W / X_b -> blocked fp16 [kc][256][32]
// ---------------------------------------------------------------------------
__global__ __launch_bounds__(256)
void cvt_blocked(const float* __restrict__ Wr, const float* __restrict__ W0,
                 const float* __restrict__ W1, const float* __restrict__ X)
{
    __shared__ float tile[32][33];
    const int id = blockIdx.x;
    const float* src; half* dst; int kc, n0;
    if (id < 96)       { kc = id >> 3; n0 = (id & 7) * 32; src = Wr; dst = g_WrB; }
    else if (id < 160) { int t = id - 96;  kc = t >> 3; n0 = (t & 7) * 32;
                         src = W0; dst = g_W0B; }
    else if (id < 224) { int t = id - 160; kc = t >> 3; n0 = (t & 7) * 32;
                         src = W1; dst = g_W1B; }
    else {
        int t = id - 224;
        int b = t >> 5, tt = t & 31;
        kc = tt >> 3; n0 = (tt & 7) * 32;
        src = X + (size_t)b * 32768;
        dst = g_XB + (size_t)b * 32768;
    }
    const int c = threadIdx.x & 31, r8 = threadIdx.x >> 5;
    #pragma unroll
    for (int p = 0; p < 4; ++p) {
        int r = r8 + p * 8;
        tile[r][c] = src[(size_t)(kc * 32 + r) * 256 + n0 + c];
    }
    __syncthreads();
    const int nl = threadIdx.x >> 3, kl0 = (threadIdx.x & 7) * 4;
    half* o = dst + ((size_t)(kc * 256 + n0 + nl) * 32 + kl0);
    half2 h0 = __floats2half2_rn(tile[kl0][nl],     tile[kl0 + 1][nl]);
    half2 h1 = __floats2half2_rn(tile[kl0 + 2][nl], tile[kl0 + 3][nl]);
    *(uint2*)o = make_uint2(h2u(h0), h2u(h1));
}

// ---------------------------------------------------------------------------
// Edge kernel: fp16 mma, FULL-TILE DOUBLE BUFFER.
// Per tile: sync -> [awb/STS(k+1), LDG(k+2)] -> 64 mma -> epilogue.
// 2 syncs/tile (was 5). 512 thr = 16 warps (4 rg x 4 cg), persistent.
// ---------------------------------------------------------------------------
#define EH_PITCH 136
#define ES_HALF  (128 * EH_PITCH)          // halfs per buffer = 17408
#define ES_OFF   0                          // two buffers: 2*34816 bytes
#define WS_OFF   69632
#define AW_OFF   104448
#define RED_OFF  105472
#define SM_BYTES 107520

__device__ __forceinline__ void compute_quarter_h(const half* __restrict__ ap,
                                                  const half* __restrict__ bp,
                                                  float acc[2][4][4])
{
    #pragma unroll
    for (int ss = 0; ss < 2; ++ss) {
        const int kb = ss * 16;
        uint32_t a[2][4];
        #pragma unroll
        for (int m = 0; m < 2; ++m) {
            const half* p = ap + m * (16 * EH_PITCH) + kb;
            a[m][0] = *(const uint32_t*)(p);
            a[m][1] = *(const uint32_t*)(p + 8 * EH_PITCH);
            a[m][2] = *(const uint32_t*)(p + 8);
            a[m][3] = *(const uint32_t*)(p + 8 * EH_PITCH + 8);
        }
        uint32_t bq[4][2];
        #pragma unroll
        for (int n = 0; n < 4; ++n) {
            const half* p = bp + n * (8 * EH_PITCH) + kb;
            bq[n][0] = *(const uint32_t*)(p);
            bq[n][1] = *(const uint32_t*)(p + 8);
        }
        #pragma unroll
        for (int m = 0; m < 2; ++m)
            #pragma unroll
            for (int n = 0; n < 4; ++n)
                mma16h(acc[m][n], a[m], bq[n]);
    }
}

__global__ __launch_bounds__(512, 1)
void edge_msg_mma(const float* __restrict__ E,
                  const float* __restrict__ A,
                  const float* __restrict__ We,
                  const float* __restrict__ be,
                  float* __restrict__ msgE)
{
    extern __shared__ char smc[];
    half*  Es  = (half*)(smc + ES_OFF);     // Es + (buf)*ES_HALF
    half*  Ws  = (half*)(smc + WS_OFF);
    float* awb = (float*)(smc + AW_OFF);
    float* red = (float*)(smc + RED_OFF);

    const int tid  = threadIdx.x;
    const int lane = tid & 31;
    const int wid  = tid >> 5;
    const int rg   = wid >> 2;
    const int cg   = wid & 3;
    const int row0 = rg * 32;
    const int col0 = cg * 32;

    float be0[4], be1[4];
    #pragma unroll
    for (int n = 0; n < 4; ++n) {
        be0[n] = be[col0 + 8 * n + 2 * (lane & 3)];
        be1[n] = be[col0 + 8 * n + 2 * (lane & 3) + 1];
    }

    // We^T -> Ws[f][e] (once); visible after first top-of-loop sync
    for (int idx = tid; idx < 8192; idx += 512) {
        int f = idx & 127;
        int e = (idx >> 7) * 2;
        *(half2*)(Ws + f * EH_PITCH + e) =
            __floats2half2_rn(We[(size_t)e * 128 + f], We[(size_t)(e + 1) * 128 + f]);
    }

    const int t0  = blockIdx.x;
    const int ntl = (NROWS - t0 + EDGE_GRID - 1) / EDGE_GRID;

    const int ech = (tid & 7) * 4;
    const int ir0 = tid >> 3;
    // full-tile load: 8 float4/thread
    auto ldt = [&](float4* r, int t) {
        const float* src = E + (size_t)(t >> 7) * 2097152
                             + (size_t)ir0 * 16384
                             + (size_t)(t & 127) * 128 + ech;
        #pragma unroll
        for (int q = 0; q < 4; ++q) {
            r[2 * q]     = *(const float4*)(src + q * 32);
            r[2 * q + 1] = *(const float4*)(src + q * 32 + (size_t)64 * 16384);
        }
    };
    auto stg = [&](const float4* r, half* base) {
        half* qd0 = base + ir0 * EH_PITCH + ech;
        #pragma unroll
        for (int q = 0; q < 4; ++q) {
            *(uint2*)(qd0 + q * 32)                 = f4toh4(r[2 * q]);
            *(uint2*)(qd0 + q * 32 + 64 * EH_PITCH) = f4toh4(r[2 * q + 1]);
        }
    };

    // prologue: buf0 <- tile0; pre <- tile1; awb[0] <- A(t0)
    float4 pre[8];
    ldt(pre, t0);
    stg(pre, Es);
    if (tid < 128)
        awb[tid] = A[(size_t)(t0 >> 7) * 16384 + (size_t)tid * 128 + (t0 & 127)];
    float awreg = 0.f;
    if (ntl > 1) {
        const int t1 = t0 + EDGE_GRID;
        ldt(pre, t1);
        if (tid < 128)
            awreg = A[(size_t)(t1 >> 7) * 16384 + (size_t)tid * 128 + (t1 & 127)];
    }

    float acc[2][4][4];
    #pragma unroll
    for (int m = 0; m < 2; ++m)
        #pragma unroll
        for (int n = 0; n < 4; ++n)
            #pragma unroll
            for (int q = 0; q < 4; ++q) acc[m][n][q] = 0.f;

    const half* aptr0 = Es + (row0 + (lane >> 2)) * EH_PITCH + (lane & 3) * 2;
    const half* bptr  = Ws + (col0 + (lane >> 2)) * EH_PITCH + (lane & 3) * 2;

    for (int k = 0; k < ntl; ++k) {
        const int t = t0 + k * EDGE_GRID;
        __syncthreads();                         // buf(k&1) + awb[k&1] staged

        // stage tile k+1 into the other buffer; prefetch tile k+2
        if (k + 1 < ntl) {
            if (tid < 128) awb[((k + 1) & 1) * 128 + tid] = awreg;
            stg(pre, Es + ((k + 1) & 1) * ES_HALF);
            if (k + 2 < ntl) {
                const int t2 = t0 + (k + 2) * EDGE_GRID;
                ldt(pre, t2);
                if (tid < 128)
                    awreg = A[(size_t)(t2 >> 7) * 16384 + (size_t)tid * 128 + (t2 & 127)];
            }
        }

        // 64 mma, uninterrupted
        const half* ap = aptr0 + (k & 1) * ES_HALF;
        #pragma unroll
        for (int q = 0; q < 4; ++q)
            compute_quarter_h(ap + q * 32, bptr + q * 32, acc);

        // ---- epilogue ----
        {
            const float* aw = awb + (k & 1) * 128;
            float p0[4], p1[4];
            #pragma unroll
            for (int n = 0; n < 4; ++n) { p0[n] = 0.f; p1[n] = 0.f; }
            #pragma unroll
            for (int m = 0; m < 2; ++m) {
                float w0 = aw[row0 + 16 * m + (lane >> 2)];
                float w1 = aw[row0 + 16 * m + (lane >> 2) + 8];
                #pragma unroll
                for (int n = 0; n < 4; ++n) {
                    p0[n] += w0 * fmaxf(acc[m][n][0] + be0[n], 0.f)
                           + w1 * fmaxf(acc[m][n][2] + be0[n], 0.f);
                    p1[n] += w0 * fmaxf(acc[m][n][1] + be1[n], 0.f)
                           + w1 * fmaxf(acc[m][n][3] + be1[n], 0.f);
                    acc[m][n][0] = 0.f; acc[m][n][1] = 0.f;
                    acc[m][n][2] = 0.f; acc[m][n][3] = 0.f;
                }
            }
            #pragma unroll
            for (int off = 4; off < 32; off <<= 1) {
                #pragma unroll
                for (int n = 0; n < 4; ++n) {
                    p0[n] += __shfl_xor_sync(0xffffffffu, p0[n], off);
                    p1[n] += __shfl_xor_sync(0xffffffffu, p1[n], off);
                }
            }
            if (rg > 0 && lane < 4) {
                #pragma unroll
                for (int n = 0; n < 4; ++n) {
                    int f = col0 + 8 * n + 2 * lane;
                    red[(rg - 1) * 128 + f]     = p0[n];
                    red[(rg - 1) * 128 + f + 1] = p1[n];
                }
            }
            __syncthreads();
            if (rg == 0 && lane < 4) {
                #pragma unroll
                for (int n = 0; n < 4; ++n) {
                    int f = col0 + 8 * n + 2 * lane;
                    msgE[(size_t)t * NE + f] =
                        p0[n] + red[f] + red[128 + f] + red[256 + f];
                    msgE[(size_t)t * NE + f + 1] =
                        p1[n] + red[f + 1] + red[128 + f + 1] + red[256 + f + 1];
                }
            }
        }
    }
}

// ---------------------------------------------------------------------------
// Fused MLP + msg_x (VERBATIM R14): fp16 mma, depth-2 weight prefetch.
// ---------------------------------------------------------------------------
#define AM_P  392
#define AST_P 136
#define FT_P  264
#define BS_P  40
#define OFF_AM  0
#define OFF_AST 12544
#define OFF_TS  16896
#define OFF_US  25344
#define OFF_BS0 33792
#define OFF_BS1 54272
#define FSM_BYTES 74752

__device__ __forceinline__ void fgemm_h(const half* __restrict__ Asm, int PA,
                                        const half* __restrict__ WB,
                                        half* __restrict__ bs0,
                                        half* __restrict__ bs1,
                                        int nch, int tid, int lane, int wcol0,
                                        float acc[4][4])
{
    const half* wsrc = WB + (size_t)tid * 32;
    uint4 pw0[4], pw1[4];
    #pragma unroll
    for (int q = 0; q < 4; ++q) pw0[q] = *(const uint4*)(wsrc + q * 8);
    if (nch > 1) {
        #pragma unroll
        for (int q = 0; q < 4; ++q) pw1[q] = *(const uint4*)(wsrc + 8192 + q * 8);
    }

    const half* apb = Asm + (lane >> 2) * PA + (lane & 3) * 2;

    for (int kc = 0; kc < nch; ++kc) {
        half* bd = ((kc & 1) ? bs1 : bs0) + tid * BS_P;
        #pragma unroll
        for (int q = 0; q < 4; ++q) *(uint4*)(bd + q * 8) = pw0[q];
        #pragma unroll
        for (int q = 0; q < 4; ++q) pw0[q] = pw1[q];
        if (kc + 2 < nch) {
            const half* ws = wsrc + (size_t)(kc + 2) * 8192;
            #pragma unroll
            for (int q = 0; q < 4; ++q) pw1[q] = *(const uint4*)(ws + q * 8);
        }
        __syncthreads();

        const half* bp = ((kc & 1) ? bs1 : bs0)
                       + (wcol0 + (lane >> 2)) * BS_P + (lane & 3) * 2;
        const half* ap = apb + kc * 32;
        #pragma unroll
        for (int ss = 0; ss < 2; ++ss) {
            const half* pa = ap + ss * 16;
            uint32_t a[4];
            a[0] = *(const uint32_t*)(pa);
            a[1] = *(const uint32_t*)(pa + 8 * PA);
            a[2] = *(const uint32_t*)(pa + 8);
            a[3] = *(const uint32_t*)(pa + 8 * PA + 8);
            uint32_t bq[4][2];
            #pragma unroll
            for (int n = 0; n < 4; ++n) {
                const half* pb = bp + n * (8 * BS_P) + ss * 16;
                bq[n][0] = *(const uint32_t*)(pb);
                bq[n][1] = *(const uint32_t*)(pb + 8);
            }
            #pragma unroll
            for (int n = 0; n < 4; ++n) mma16h(acc[n], a, bq[n]);
        }
    }
}

__global__ __launch_bounds__(256)
void mlp_fused(const float* __restrict__ msgE,
               const float* __restrict__ X,
               const float* __restrict__ A,
               const float* __restrict__ epsp,
               const float* __restrict__ br, const float* __restrict__ b0,
               const float* __restrict__ b1,
               float* __restrict__ Out)
{
    extern __shared__ char fsc[];
    half* Am  = (half*)(fsc + OFF_AM);
    half* AsT = (half*)(fsc + OFF_AST);
    half* Ts  = (half*)(fsc + OFF_TS);
    half* Us  = (half*)(fsc + OFF_US);
    half* Bs0 = (half*)(fsc + OFF_BS0);
    half* Bs1 = (half*)(fsc + OFF_BS1);

    const int r0   = blockIdx.x * 16;
    const int b    = r0 >> 7;
    const int j0   = r0 & 127;
    const int tid  = threadIdx.x;
    const int lane = tid & 31;
    const int wid  = tid >> 5;
    const int wcol0 = wid * 32;

    for (int idx = tid; idx < 2048; idx += 256) {
        int i = idx >> 4, jj = idx & 15;
        AsT[jj * AST_P + i] =
            __float2half(A[(size_t)b * 16384 + (size_t)i * 128 + j0 + jj]);
    }
    {
        const int row = tid >> 4;
        const int c   = (tid & 15) * 8;
        const float* src = msgE + (size_t)(r0 + row) * NE + c;
        half* dst = Am + row * AM_P + 256 + c;
        *(uint2*)(dst)     = f4toh4(*(const float4*)(src));
        *(uint2*)(dst + 4) = f4toh4(*(const float4*)(src + 4));
    }
    __syncthreads();

    float acc[4][4];
    #pragma unroll
    for (int n = 0; n < 4; ++n)
        #pragma unroll
        for (int q = 0; q < 4; ++q) acc[n][q] = 0.f;

    const int erow = lane >> 2;
    const int ecol = 2 * (lane & 3);

    // ---- msg_x = AsT @ X_b -> Am cols 0..255 ----
    fgemm_h(AsT, AST_P, g_XB + (size_t)b * 32768, Bs0, Bs1,
            4, tid, lane, wcol0, acc);
    #pragma unroll
    for (int n = 0; n < 4; ++n) {
        int col = wcol0 + 8 * n + ecol;
        *(uint32_t*)(Am + erow * AM_P + col) =
            h2u(__floats2half2_rn(acc[n][0], acc[n][1]));
        *(uint32_t*)(Am + (erow + 8) * AM_P + col) =
            h2u(__floats2half2_rn(acc[n][2], acc[n][3]));
        acc[n][0] = acc[n][1] = acc[n][2] = acc[n][3] = 0.f;
    }
    __syncthreads();

    // ---- layer 1: t = (1+eps)*X + relu(Am@Wr + br) ----
    fgemm_h(Am, AM_P, g_WrB, Bs0, Bs1, 12, tid, lane, wcol0, acc);
    {
        const float epsv = 1.f + *epsp;
        #pragma unroll
        for (int n = 0; n < 4; ++n) {
            int col = wcol0 + 8 * n + ecol;
            float v00 = fmaxf(acc[n][0] + br[col], 0.f)
                      + epsv * X[(size_t)(r0 + erow) * 256 + col];
            float v01 = fmaxf(acc[n][1] + br[col + 1], 0.f)
                      + epsv * X[(size_t)(r0 + erow) * 256 + col + 1];
            float v10 = fmaxf(acc[n][2] + br[col], 0.f)
                      + epsv * X[(size_t)(r0 + erow + 8) * 256 + col];
            float v11 = fmaxf(acc[n][3] + br[col + 1], 0.f)
                      + epsv * X[(size_t)(r0 + erow + 8) * 256 + col + 1];
            *(uint32_t*)(Ts + erow * FT_P + col)       = h2u(__floats2half2_rn(v00, v01));
            *(uint32_t*)(Ts + (erow + 8) * FT_P + col) = h2u(__floats2half2_rn(v10, v11));
            acc[n][0] = acc[n][1] = acc[n][2] = acc[n][3] = 0.f;
        }
    }
    __syncthreads();

    // ---- layer 2: u = relu(t@W0 + b0) ----
    fgemm_h(Ts, FT_P, g_W0B, Bs0, Bs1, 8, tid, lane, wcol0, acc);
    #pragma unroll
    for (int n = 0; n < 4; ++n) {
        int col = wcol0 + 8 * n + ecol;
        *(uint32_t*)(Us + erow * FT_P + col) = h2u(__floats2half2_rn(
            fmaxf(acc[n][0] + b0[col], 0.f), fmaxf(acc[n][1] + b0[col + 1], 0.f)));
        *(uint32_t*)(Us + (erow + 8) * FT_P + col) = h2u(__floats2half2_rn(
            fmaxf(acc[n][2] + b0[col], 0.f), fmaxf(acc[n][3] + b0[col + 1], 0.f)));
        acc[n][0] = acc[n][1] = acc[n][2] = acc[n][3] = 0.f;
    }
    __syncthreads();

    // ---- layer 3: out = relu(u@W1 + b1) ----
    fgemm_h(Us, FT_P, g_W1B, Bs0, Bs1, 8, tid, lane, wcol0, acc);
    #pragma unroll
    for (int n = 0; n < 4; ++n) {
        int col = wcol0 + 8 * n + ecol;
        float2 v0 = make_float2(fmaxf(acc[n][0] + b1[col], 0.f),
                                fmaxf(acc[n][1] + b1[col + 1], 0.f));
        float2 v1 = make_float2(fmaxf(acc[n][2] + b1[col], 0.f),
                                fmaxf(acc[n][3] + b1[col + 1], 0.f));
        *(float2*)(Out + (size_t)(r0 + erow) * 256 + col)     = v0;
        *(float2*)(Out + (size_t)(r0 + erow + 8) * 256 + col) = v1;
    }
}

// ---------------------------------------------------------------------------
extern "C" void kernel_launch(void* const* d_in, const int* in_sizes, int n_in,
                              void* d_out, int out_size)
{
    const float* X   = (const float*)d_in[0];
    const float* E   = (const float*)d_in[1];
    const float* A   = (const float*)d_in[2];
    const float* eps = (const float*)d_in[3];
    const float* We  = (const float*)d_in[4];
    const float* be  = (const float*)d_in[5];
    const float* Wr  = (const float*)d_in[6];
    const float* br  = (const float*)d_in[7];
    const float* W0  = (const float*)d_in[8];
    const float* b0  = (const float*)d_in[9];
    const float* W1  = (const float*)d_in[10];
    const float* b1  = (const float*)d_in[11];
    float* out = (float*)d_out;

    void* pmsg;
    cudaGetSymbolAddress(&pmsg, g_msgE);
    float* msgE = (float*)pmsg;

    cudaFuncSetAttribute(edge_msg_mma,
                         cudaFuncAttributeMaxDynamicSharedMemorySize, SM_BYTES);
    cudaFuncSetAttribute(mlp_fused,
                         cudaFuncAttributeMaxDynamicSharedMemorySize, FSM_BYTES);

    cvt_blocked<<<736, 256>>>(Wr, W0, W1, X);
    edge_msg_mma<<<EDGE_GRID, 512, SM_BYTES>>>(E, A, We, be, msgE);
    mlp_fused<<<128, 256, FSM_BYTES>>>(msgE, X, A, eps, br, b0, b1, out);
}